// round 9
// baseline (speedup 1.0000x reference)
#include <cuda_runtime.h>
#include <cstdint>

// Problem constants (fixed by the reference)
#define NUM_ROI 148
#define QQ      5
#define NN      131072

// Write-burst aggregation: 512-thread blocks so each block's store cohort
// covers 8KB contiguous per output region per ROI step (vs 2KB at TPB=128),
// and concurrent DRAM write streams drop 2048 -> 512. Same total warps as
// the best-replay config (4096). ROI split x4 keeps occupancy high;
// duplicated Z reads are L2-resident (Z = 2.6 MB).
#define TPB        512
#define N_PER_THR  4
#define ROI_SPLIT  4
#define ROI_PER_BLK (NUM_ROI / ROI_SPLIT)  // 37

__global__ __launch_bounds__(TPB) void coconet_kernel(
    const float* __restrict__ X,    // [N, 1]
    const float* __restrict__ Z,    // [N, 5]
    const float* __restrict__ Wr,   // [148, 5]
    const float* __restrict__ br,   // [148]
    const float* __restrict__ Wf,   // [148, 6]
    const float* __restrict__ bf,   // [148]
    float* __restrict__ out)        // [2, 148, N] : r_out then f_out
{
    // Packed per-ROI weights for this block's 37 ROIs: 4 x float4 per ROI
    //  w0 = {Wf0, Wf1, Wf2, Wf3}
    //  w1 = {Wf4, Wf5, bf,  br }
    //  w2 = {Wr0, Wr1, Wr2, Wr3}
    //  w3 = {Wr4, 0,   0,   0  }
    __shared__ float4 wsh[ROI_PER_BLK][4];

    const int tid      = threadIdx.x;
    const int roi_base = blockIdx.y * ROI_PER_BLK;

    if (tid < ROI_PER_BLK) {
        const int roi = roi_base + tid;
        const float* wf = Wf + roi * 6;
        const float* wr = Wr + roi * 5;
        wsh[tid][0] = make_float4(wf[0], wf[1], wf[2], wf[3]);
        wsh[tid][1] = make_float4(wf[4], wf[5], bf[roi], br[roi]);
        wsh[tid][2] = make_float4(wr[0], wr[1], wr[2], wr[3]);
        wsh[tid][3] = make_float4(wr[4], 0.f, 0.f, 0.f);
    }
    __syncthreads();

    const int n0 = (blockIdx.x * TPB + tid) * N_PER_THR;

    // Vectorized input loads: X[n0..n0+3] = 1 float4; Z rows n0..n0+3 are
    // 20 contiguous floats starting at Z + 5*n0 (16B-aligned since n0 % 4 == 0)
    // = 5 float4 loads.
    const float4 xv = __ldg(reinterpret_cast<const float4*>(X + n0));
    const float x[N_PER_THR] = {xv.x, xv.y, xv.z, xv.w};

    float zb[N_PER_THR * QQ];
    {
        const float4* zp4 = reinterpret_cast<const float4*>(Z + (size_t)n0 * QQ);
#pragma unroll
        for (int i = 0; i < 5; ++i) {
            const float4 v = __ldg(zp4 + i);
            zb[4 * i + 0] = v.x;
            zb[4 * i + 1] = v.y;
            zb[4 * i + 2] = v.z;
            zb[4 * i + 3] = v.w;
        }
    }
    // z[j][q] == zb[5*j + q]

    float* __restrict__ out_r = out + (size_t)roi_base * NN;
    float* __restrict__ out_f = out + (size_t)(NUM_ROI + roi_base) * NN;

#pragma unroll 1
    for (int r = 0; r < ROI_PER_BLK; ++r) {
        const float4 a = wsh[r][0];
        const float4 b = wsh[r][1];
        const float4 c = wsh[r][2];
        const float4 d = wsh[r][3];

        float rv[N_PER_THR], fv[N_PER_THR];
#pragma unroll
        for (int j = 0; j < N_PER_THR; ++j) {
            const float z0 = zb[5 * j + 0];
            const float z1 = zb[5 * j + 1];
            const float z2 = zb[5 * j + 2];
            const float z3 = zb[5 * j + 3];
            const float z4 = zb[5 * j + 4];
            // f_out = bf + Wf[0]*X + Wf[1..5] . Z
            float f = b.z;
            f = fmaf(a.x, x[j], f);
            f = fmaf(a.y, z0, f);
            f = fmaf(a.z, z1, f);
            f = fmaf(a.w, z2, f);
            f = fmaf(b.x, z3, f);
            f = fmaf(b.y, z4, f);
            fv[j] = f;
            // r_out = br + Wr . Z
            float rr = b.w;
            rr = fmaf(c.x, z0, rr);
            rr = fmaf(c.y, z1, rr);
            rr = fmaf(c.z, z2, rr);
            rr = fmaf(c.w, z3, rr);
            rr = fmaf(d.x, z4, rr);
            rv[j] = rr;
        }

        const size_t off = (size_t)r * NN + n0;
        __stcs(reinterpret_cast<float4*>(out_r + off),
               make_float4(rv[0], rv[1], rv[2], rv[3]));
        __stcs(reinterpret_cast<float4*>(out_f + off),
               make_float4(fv[0], fv[1], fv[2], fv[3]));
    }
}

extern "C" void kernel_launch(void* const* d_in, const int* in_sizes, int n_in,
                              void* d_out, int out_size)
{
    const float* X  = (const float*)d_in[0];
    const float* Z  = (const float*)d_in[1];
    const float* Wr = (const float*)d_in[2];
    const float* br = (const float*)d_in[3];
    const float* Wf = (const float*)d_in[4];
    const float* bf = (const float*)d_in[5];
    float* out = (float*)d_out;

    dim3 grid(NN / (TPB * N_PER_THR), ROI_SPLIT);  // (64, 4)
    coconet_kernel<<<grid, TPB>>>(X, Z, Wr, br, Wf, bf, out);
}

// round 10
// speedup vs baseline: 1.0296x; 1.0296x over previous
#include <cuda_runtime.h>
#include <cstdint>

// FINAL KERNEL — CoCoNet_72249939853425 (GB300 / sm_103a)
//
// Problem: 148 per-ROI GEMVs over N=131072 rows (K=5 and K=6), output
// [2,148,N] fp32 = 155 MB. Purely DRAM-write-bound: replay period equals
// output_bytes / ~5.3 TB/s pure-write drain (measured invariant across
// occupancy 11-40%, 512-2048 write streams, .cs/.wb/.wt, STG.64/128).
//
// Config (best measured): 256 CTAs x 128 threads, 4 consecutive n per
// thread, fully vectorized inputs (6x LDG.128/thread), smem-packed weights,
// __stcs float4 stores.
#define NUM_ROI 148
#define QQ      5
#define NN      131072

#define TPB        128
#define N_PER_THR  4

__global__ __launch_bounds__(TPB) void coconet_kernel(
    const float* __restrict__ X,    // [N, 1]
    const float* __restrict__ Z,    // [N, 5]
    const float* __restrict__ Wr,   // [148, 5]
    const float* __restrict__ br,   // [148]
    const float* __restrict__ Wf,   // [148, 6]
    const float* __restrict__ bf,   // [148]
    float* __restrict__ out)        // [2, 148, N] : r_out then f_out
{
    // Packed per-ROI weights: 4 x float4 per ROI
    //  w0 = {Wf0, Wf1, Wf2, Wf3}
    //  w1 = {Wf4, Wf5, bf,  br }
    //  w2 = {Wr0, Wr1, Wr2, Wr3}
    //  w3 = {Wr4, 0,   0,   0  }
    __shared__ float4 wsh[NUM_ROI][4];

    const int tid = threadIdx.x;

    for (int i = tid; i < NUM_ROI; i += TPB) {
        const float* wf = Wf + i * 6;
        const float* wr = Wr + i * 5;
        wsh[i][0] = make_float4(wf[0], wf[1], wf[2], wf[3]);
        wsh[i][1] = make_float4(wf[4], wf[5], bf[i], br[i]);
        wsh[i][2] = make_float4(wr[0], wr[1], wr[2], wr[3]);
        wsh[i][3] = make_float4(wr[4], 0.f, 0.f, 0.f);
    }
    __syncthreads();

    const int n0 = (blockIdx.x * TPB + tid) * N_PER_THR;

    // Vectorized input loads: X[n0..n0+3] = 1 float4; Z rows n0..n0+3 are
    // 20 contiguous floats starting at Z + 5*n0 (16B-aligned since n0 % 4 == 0)
    // = 5 float4 loads.
    const float4 xv = __ldg(reinterpret_cast<const float4*>(X + n0));
    const float x[N_PER_THR] = {xv.x, xv.y, xv.z, xv.w};

    float zb[N_PER_THR * QQ];
    {
        const float4* zp4 = reinterpret_cast<const float4*>(Z + (size_t)n0 * QQ);
#pragma unroll
        for (int i = 0; i < 5; ++i) {
            const float4 v = __ldg(zp4 + i);
            zb[4 * i + 0] = v.x;
            zb[4 * i + 1] = v.y;
            zb[4 * i + 2] = v.z;
            zb[4 * i + 3] = v.w;
        }
    }
    // z[j][q] == zb[5*j + q]

    float* __restrict__ out_r = out;
    float* __restrict__ out_f = out + (size_t)NUM_ROI * NN;

#pragma unroll 2
    for (int r = 0; r < NUM_ROI; ++r) {
        const float4 a = wsh[r][0];
        const float4 b = wsh[r][1];
        const float4 c = wsh[r][2];
        const float4 d = wsh[r][3];

        float rv[N_PER_THR], fv[N_PER_THR];
#pragma unroll
        for (int j = 0; j < N_PER_THR; ++j) {
            const float z0 = zb[5 * j + 0];
            const float z1 = zb[5 * j + 1];
            const float z2 = zb[5 * j + 2];
            const float z3 = zb[5 * j + 3];
            const float z4 = zb[5 * j + 4];
            // f_out = bf + Wf[0]*X + Wf[1..5] . Z
            float f = b.z;
            f = fmaf(a.x, x[j], f);
            f = fmaf(a.y, z0, f);
            f = fmaf(a.z, z1, f);
            f = fmaf(a.w, z2, f);
            f = fmaf(b.x, z3, f);
            f = fmaf(b.y, z4, f);
            fv[j] = f;
            // r_out = br + Wr . Z
            float rr = b.w;
            rr = fmaf(c.x, z0, rr);
            rr = fmaf(c.y, z1, rr);
            rr = fmaf(c.z, z2, rr);
            rr = fmaf(c.w, z3, rr);
            rr = fmaf(d.x, z4, rr);
            rv[j] = rr;
        }

        const size_t off = (size_t)r * NN + n0;
        __stcs(reinterpret_cast<float4*>(out_r + off),
               make_float4(rv[0], rv[1], rv[2], rv[3]));
        __stcs(reinterpret_cast<float4*>(out_f + off),
               make_float4(fv[0], fv[1], fv[2], fv[3]));
    }
}

extern "C" void kernel_launch(void* const* d_in, const int* in_sizes, int n_in,
                              void* d_out, int out_size)
{
    const float* X  = (const float*)d_in[0];
    const float* Z  = (const float*)d_in[1];
    const float* Wr = (const float*)d_in[2];
    const float* br = (const float*)d_in[3];
    const float* Wf = (const float*)d_in[4];
    const float* bf = (const float*)d_in[5];
    float* out = (float*)d_out;

    const int grid = NN / (TPB * N_PER_THR);  // 256
    coconet_kernel<<<grid, TPB>>>(X, Z, Wr, br, Wf, bf, out);
}